// round 15
// baseline (speedup 1.0000x reference)
#include <cuda_runtime.h>
#include <cuda_bf16.h>
#include <math.h>

// ---------------- Problem dims ----------------
#define NL    8
#define BSZ   8
#define LSEQ  1024
#define DM    256
#define DI    512
#define NST   16
#define DTR   16
#define PROJC 48
#define MROWS (BSZ*LSEQ)  // 8192

// ---------------- Device scratch ----------------
__device__ float g_h   [MROWS*DM];
__device__ float g_xz  [MROWS*2*DI];
__device__ float g_proj[MROWS*PROJC];
__device__ float g_ymod[MROWS*DI];
__device__ float g_out2[MROWS*DM];
__device__ float g_pooled[BSZ*DM];

// ---------------- helpers ----------------
__device__ __forceinline__ void mma_tf32(float& d0, float& d1, float& d2, float& d3,
                                         unsigned a0, unsigned a1, unsigned a2, unsigned a3,
                                         unsigned b0, unsigned b1) {
    asm volatile(
        "mma.sync.aligned.m16n8k8.row.col.f32.tf32.tf32.f32 "
        "{%0,%1,%2,%3}, {%4,%5,%6,%7}, {%8,%9}, {%0,%1,%2,%3};\n"
        : "+f"(d0), "+f"(d1), "+f"(d2), "+f"(d3)
        : "r"(a0), "r"(a1), "r"(a2), "r"(a3), "r"(b0), "r"(b1));
}
__device__ __forceinline__ void cp16(unsigned dst, const void* src) {
    asm volatile("cp.async.cg.shared.global [%0], [%1], 16;\n" :: "r"(dst), "l"(src));
}
__device__ __forceinline__ void cp_commit() { asm volatile("cp.async.commit_group;\n"); }
__device__ __forceinline__ void cp_wait0()  { asm volatile("cp.async.wait_group 0;\n"); }
__device__ __forceinline__ void cp_wait1()  { asm volatile("cp.async.wait_group 1;\n"); }
__device__ __forceinline__ void cp_wait2()  { asm volatile("cp.async.wait_group 2;\n"); }

// ---------------- Encoder ----------------
__global__ void enc_kernel(const float* __restrict__ x,
                           const float* __restrict__ w,
                           const float* __restrict__ bb) {
    int bl = blockIdx.x;
    int m  = threadIdx.x;
    int b = bl >> 10, l = bl & 1023;
    float acc = bb[m];
#pragma unroll
    for (int c = 0; c < 3; c++)
        acc = fmaf(x[(b*3 + c)*LSEQ + l], w[c*DM + m], acc);
    g_h[bl*DM + m] = acc;
}

// ---------------- TF32 GEMM, cp.async 4-stage pipeline (in_proj / out_proj) -------
#define ASTR 20
#define BSTR 72
template<int BM>
__global__ void __launch_bounds__(256, 2)
gemm_tf32_cp(const float* __restrict__ A,
             const float* __restrict__ B,
             float* __restrict__ C,
             int M, int N, int K) {
    constexpr int AM = BM / 64;
    __shared__ unsigned As[4][BM*ASTR];
    __shared__ unsigned Bs[4][16*BSTR];

    const int tid  = threadIdx.x;
    const int lane = tid & 31;
    const int wid  = tid >> 5;
    const int wm   = wid & 3;
    const int wn   = wid >> 2;
    const int m0   = blockIdx.y * BM;
    const int n0   = blockIdx.x * 64;
    const int r = lane >> 2;
    const int c = lane & 3;

    const int bRow = tid >> 4;
    const int bNq  = tid & 15;
    const bool bOk = (n0 + bNq*4 + 3) < N;

    unsigned aBase[4], bBase[4];
#pragma unroll
    for (int s = 0; s < 4; s++) {
        aBase[s] = (unsigned)__cvta_generic_to_shared(&As[s][0]);
        bBase[s] = (unsigned)__cvta_generic_to_shared(&Bs[s][0]);
    }

    auto loadTile = [&](int t, int s) {
        int k0 = t * 16;
#pragma unroll
        for (int j = 0; j < AM; j++) {
            int slot = j*256 + tid;
            int row = slot >> 2, kq = slot & 3;
            cp16(aBase[s] + (row*ASTR + kq*4)*4,
                 A + (size_t)(m0 + row)*K + k0 + kq*4);
        }
        if (bOk)
            cp16(bBase[s] + (bRow*BSTR + bNq*4)*4,
                 B + (size_t)(k0 + bRow)*N + n0 + bNq*4);
        cp_commit();
    };

    float acc[AM][4][4] = {};
    const int T = K >> 4;

    loadTile(0, 0); loadTile(1, 1); loadTile(2, 2);

    for (int t = 0; t < T; t++) {
        int cur = t & 3;
        cp_wait2();
        __syncthreads();
        if (t + 3 < T) loadTile(t + 3, (t + 3) & 3);
        else           cp_commit();

        const unsigned* Ab = As[cur];
        const unsigned* Bb = Bs[cur];
#pragma unroll
        for (int kk = 0; kk < 16; kk += 8) {
            unsigned af[AM][4], bf[4][2];
#pragma unroll
            for (int am = 0; am < AM; am++) {
                int mrow = wm*(BM/4) + am*16;
                af[am][0] = Ab[(mrow + r    )*ASTR + kk + c    ];
                af[am][1] = Ab[(mrow + r + 8)*ASTR + kk + c    ];
                af[am][2] = Ab[(mrow + r    )*ASTR + kk + c + 4];
                af[am][3] = Ab[(mrow + r + 8)*ASTR + kk + c + 4];
            }
#pragma unroll
            for (int bn = 0; bn < 4; bn++) {
                int ncol = wn*32 + bn*8 + r;
                bf[bn][0] = Bb[(kk + c    )*BSTR + ncol];
                bf[bn][1] = Bb[(kk + c + 4)*BSTR + ncol];
            }
#pragma unroll
            for (int am = 0; am < AM; am++)
#pragma unroll
                for (int bn = 0; bn < 4; bn++)
                    mma_tf32(acc[am][bn][0], acc[am][bn][1], acc[am][bn][2], acc[am][bn][3],
                             af[am][0], af[am][1], af[am][2], af[am][3],
                             bf[bn][0], bf[bn][1]);
        }
    }

#pragma unroll
    for (int am = 0; am < AM; am++) {
#pragma unroll
        for (int bn = 0; bn < 4; bn++) {
            int m = m0 + wm*(BM/4) + am*16 + r;
            int n = n0 + wn*32 + bn*8 + 2*c;
            if (n + 1 < N) {
                *(float2*)(C + (size_t)m*N + n)       = make_float2(acc[am][bn][0], acc[am][bn][1]);
                *(float2*)(C + (size_t)(m + 8)*N + n) = make_float2(acc[am][bn][2], acc[am][bn][3]);
            } else if (n < N) {
                C[(size_t)m*N + n]       = acc[am][bn][0];
                C[(size_t)(m + 8)*N + n] = acc[am][bn][2];
            }
        }
    }
}

// ---------------- x_proj GEMM with fused conv+SiLU on the A path ----------------
#define RSTR 20
__global__ void __launch_bounds__(256)
xproj_conv_gemm(const float* __restrict__ xz,
                const float* __restrict__ W,
                float* __restrict__ Cout,
                const float* __restrict__ cw,
                const float* __restrict__ cb) {
    __shared__ unsigned As[64*RSTR];
    __shared__ float    Raw[3][67*RSTR];
    __shared__ unsigned Bs[3][16*BSTR];
    __shared__ float    scw[DI*4];
    __shared__ float    scb[DI];

    const int tid  = threadIdx.x;
    const int lane = tid & 31;
    const int wid  = tid >> 5;
    const int wm   = wid & 3;
    const int wn   = wid >> 2;
    const int m0   = blockIdx.y * 64;
    const int r = lane >> 2;
    const int c = lane & 3;

    for (int i = tid; i < 3*16*BSTR; i += 256) (&Bs[0][0])[i] = 0u;
    for (int i = tid; i < DI*4; i += 256) scw[i] = cw[i];
    for (int i = tid; i < DI;   i += 256) scb[i] = cb[i];
    const bool hz = (m0 & 1023) == 0;
    if (hz) {
#pragma unroll
        for (int s = 0; s < 3; s++)
            if (tid < 48) Raw[s][(tid >> 4)*RSTR + (tid & 15)] = 0.f;
    }
    __syncthreads();

    const int i1 = tid >> 2, q1 = tid & 3;
    const int bRow = tid >> 4;
    const int bNq  = tid & 15;
    const bool bOk = bNq < 12;

    unsigned rawB[3], bsB[3];
#pragma unroll
    for (int s = 0; s < 3; s++) {
        rawB[s] = (unsigned)__cvta_generic_to_shared(&Raw[s][0]);
        bsB[s]  = (unsigned)__cvta_generic_to_shared(&Bs[s][0]);
    }

    auto loadT = [&](int t, int s) {
        int k0 = t * 16;
        if (!hz || i1 >= 3)
            cp16(rawB[s] + (i1*RSTR + q1*4)*4,
                 xz + (size_t)(m0 - 3 + i1)*(2*DI) + k0 + q1*4);
        if (tid < 12) {
            int i2 = 64 + (tid >> 2);
            cp16(rawB[s] + (i2*RSTR + (tid & 3)*4)*4,
                 xz + (size_t)(m0 - 3 + i2)*(2*DI) + k0 + (tid & 3)*4);
        }
        if (bOk)
            cp16(bsB[s] + (bRow*BSTR + bNq*4)*4,
                 W + (size_t)(k0 + bRow)*PROJC + bNq*4);
        cp_commit();
    };

    float acc[4][4] = {};
    const int T = DI >> 4;

    loadT(0, 0); loadT(1, 1);

    for (int t = 0; t < T; t++) {
        int cur = t % 3;
        cp_wait1();
        __syncthreads();
        if (t + 2 < T) loadT(t + 2, (t + 2) % 3);
        else           cp_commit();

        {
            const float* R = Raw[cur];
            int row = tid >> 2;
            int cb4 = (tid & 3) * 4;
#pragma unroll
            for (int j = 0; j < 4; j++) {
                int cc = cb4 + j;
                int d  = t*16 + cc;
                float a = scb[d];
#pragma unroll
                for (int k = 0; k < 4; k++)
                    a = fmaf(R[(row + k)*RSTR + cc], scw[d*4 + k], a);
                a = a / (1.f + __expf(-a));
                As[row*RSTR + cc] = __float_as_uint(a);
            }
        }
        __syncthreads();

        const unsigned* Bb = Bs[cur];
#pragma unroll
        for (int kk = 0; kk < 16; kk += 8) {
            unsigned af[4], bf[4][2];
            {
                int mrow = wm*16;
                af[0] = As[(mrow + r    )*RSTR + kk + c    ];
                af[1] = As[(mrow + r + 8)*RSTR + kk + c    ];
                af[2] = As[(mrow + r    )*RSTR + kk + c + 4];
                af[3] = As[(mrow + r + 8)*RSTR + kk + c + 4];
            }
#pragma unroll
            for (int bn = 0; bn < 4; bn++) {
                int ncol = wn*32 + bn*8 + r;
                bf[bn][0] = Bb[(kk + c    )*BSTR + ncol];
                bf[bn][1] = Bb[(kk + c + 4)*BSTR + ncol];
            }
#pragma unroll
            for (int bn = 0; bn < 4; bn++)
                mma_tf32(acc[bn][0], acc[bn][1], acc[bn][2], acc[bn][3],
                         af[0], af[1], af[2], af[3],
                         bf[bn][0], bf[bn][1]);
        }
    }

#pragma unroll
    for (int bn = 0; bn < 4; bn++) {
        int m = m0 + wm*16 + r;
        int n = wn*32 + bn*8 + 2*c;
        if (n + 1 < PROJC) {
            *(float2*)(Cout + (size_t)m*PROJC + n)       = make_float2(acc[bn][0], acc[bn][1]);
            *(float2*)(Cout + (size_t)(m + 8)*PROJC + n) = make_float2(acc[bn][2], acc[bn][3]);
        } else if (n < PROJC) {
            Cout[(size_t)m*PROJC + n]       = acc[bn][0];
            Cout[(size_t)(m + 8)*PROJC + n] = acc[bn][2];
        }
    }
}

// ---------------- Fused conv + dt + scan, transpose-reduce v2 ----------------
// Serial loop stashes RAW state; C is applied in the group reduce (dot of
// state row with C row). exp/shfl batched per 8 steps -> flat serial chain.
#define SCH 64
#define SPSTR 52
#define PSTR 36
__global__ void __launch_bounds__(256)
scan_kernel(const float* __restrict__ A_log,
            const float* __restrict__ Dv,
            const float* __restrict__ dtw,
            const float* __restrict__ dtb,
            const float* __restrict__ cw,
            const float* __restrict__ cb) {
    __shared__ float sp[2][SCH*SPSTR];   // proj rows        26.6 KB
    __shared__ float rx[2][67*16];       // raw x + halo      8.6 KB
    __shared__ float sz[2][SCH*16];      // raw z             8.2 KB
    __shared__ float su2[SCH*16];        // u; reused as y    4.1 KB
    __shared__ float sgg[SCH*32];        // gate, u*D*gate    8.2 KB
    __shared__ float psh[8*16*PSTR];     // state tile       18.4 KB
    __shared__ float sDv[16];

    const int b  = blockIdx.x >> 5;
    const int d0 = (blockIdx.x & 31) * 16;
    const int tid = threadIdx.x;
    const int hw = tid >> 4;
    const int n  = tid & 15;
    const int lane = tid & 31;
    const int wid  = tid >> 5;
    const int d  = d0 + hw;
    const int hbase = lane & 16;
    const int blbase = b << 10;

    const int rl = tid >> 2;
    const int rq = tid & 3;

    const int ccol = (tid & 3) * 4;
    float wv[4][4], bv[4];
#pragma unroll
    for (int j = 0; j < 4; j++) {
        bv[j] = cb[d0 + ccol + j];
#pragma unroll
        for (int k = 0; k < 4; k++)
            wv[j][k] = cw[(d0 + ccol + j)*4 + k];
    }
    if (tid < 16) sDv[tid] = Dv[d0 + tid];
    if (tid < 48) rx[0][tid] = 0.f;

    unsigned spB[2], rxB[2], szB[2];
#pragma unroll
    for (int s = 0; s < 2; s++) {
        spB[s] = (unsigned)__cvta_generic_to_shared(&sp[s][0]);
        rxB[s] = (unsigned)__cvta_generic_to_shared(&rx[s][0]);
        szB[s] = (unsigned)__cvta_generic_to_shared(&sz[s][0]);
    }

    auto loadChunk = [&](int c0, int buf) {
        cp16(rxB[buf] + (rl*16 + rq*4)*4,
             g_xz + (size_t)(blbase + c0 - 3 + rl)*(2*DI) + d0 + rq*4);
        if (tid < 12) {
            int i2 = 64 + (tid >> 2);
            cp16(rxB[buf] + (i2*16 + (tid & 3)*4)*4,
                 g_xz + (size_t)(blbase + c0 - 3 + i2)*(2*DI) + d0 + (tid & 3)*4);
        }
        cp16(szB[buf] + (rl*16 + rq*4)*4,
             g_xz + (size_t)(blbase + c0 + rl)*(2*DI) + DI + d0 + rq*4);
#pragma unroll
        for (int k = 0; k < 3; k++) {
            int s = tid + k*256;
            int l = s / 12, q = s - l*12;
            cp16(spB[buf] + (l*SPSTR + q*4)*4,
                 g_proj + (size_t)(blbase + c0 + l)*PROJC + q*4);
        }
        cp_commit();
    };
    auto loadChunk0 = [&]() {
        if (rl >= 3)
            cp16(rxB[0] + (rl*16 + rq*4)*4,
                 g_xz + (size_t)(blbase - 3 + rl)*(2*DI) + d0 + rq*4);
        if (tid < 12) {
            int i2 = 64 + (tid >> 2);
            cp16(rxB[0] + (i2*16 + (tid & 3)*4)*4,
                 g_xz + (size_t)(blbase - 3 + i2)*(2*DI) + d0 + (tid & 3)*4);
        }
        cp16(szB[0] + (rl*16 + rq*4)*4,
             g_xz + (size_t)(blbase + rl)*(2*DI) + DI + d0 + rq*4);
#pragma unroll
        for (int k = 0; k < 3; k++) {
            int s = tid + k*256;
            int l = s / 12, q = s - l*12;
            cp16(spB[0] + (l*SPSTR + q*4)*4,
                 g_proj + (size_t)(blbase + l)*PROJC + q*4);
        }
        cp_commit();
    };

    float wdt[DTR];
#pragma unroll
    for (int r = 0; r < DTR; r++) wdt[r] = dtw[r*DI + d];
    const float dtbv = dtb[d];
    const float Ad = -__expf(A_log[d*NST + n]);
    float state = 0.f;

    float* psw = &psh[wid*16*PSTR];

    loadChunk0();

    for (int cc = 0; cc < LSEQ/SCH; cc++) {
        int buf = cc & 1;
        if (cc + 1 < LSEQ/SCH) { loadChunk((cc+1)*SCH, buf ^ 1); cp_wait1(); }
        else                   { cp_wait0(); }
        __syncthreads();

        const float* P = sp[buf];
        const float* X = rx[buf];
        const float* Z = sz[buf];

        // dt for steps {j*16+n}
        float dtv4[4];
#pragma unroll
        for (int j = 0; j < 4; j++) {
            float a = dtbv;
            const float* row = &P[(j*16 + n)*SPSTR];
#pragma unroll
            for (int r = 0; r < DTR; r++) a = fmaf(row[r], wdt[r], a);
            dtv4[j] = (a > 20.f) ? a : __logf(1.f + __expf(a));
        }

        // convert: u, gate, g2 = u*D*gate
#pragma unroll
        for (int j = 0; j < 4; j++) {
            int c2 = ccol + j;
            float a = bv[j];
#pragma unroll
            for (int k = 0; k < 4; k++)
                a = fmaf(X[(rl + k)*16 + c2], wv[j][k], a);
            float u = a / (1.f + __expf(-a));
            su2[rl*16 + c2] = u;
            float zz = Z[rl*16 + c2];
            float gate = zz / (1.f + __expf(-zz));
            sgg[rl*32 + c2*2    ] = gate;
            sgg[rl*32 + c2*2 + 1] = u * sDv[c2] * gate;
        }
        __syncthreads();

        // serial loop: 16-step groups, exp/shfl batched per 8 steps
#pragma unroll
        for (int g = 0; g < SCH/16; g++) {
#pragma unroll
            for (int h = 0; h < 2; h++) {
                float da[8], ea[8];
#pragma unroll
                for (int i = 0; i < 8; i++)
                    da[i] = __shfl_sync(0xffffffffu, dtv4[g], hbase + h*8 + i, 32);
#pragma unroll
                for (int i = 0; i < 8; i++)
                    ea[i] = __expf(da[i]*Ad);
#pragma unroll
                for (int i = 0; i < 8; i++) {
                    int l = g*16 + h*8 + i;
                    float uv = su2[l*16 + hw];
                    float Bv = P[l*SPSTR + DTR + n];
                    state = fmaf(ea[i], state, da[i]*uv*Bv);
                    psw[(h*8 + i)*PSTR + lane] = state;
                }
            }
            __syncwarp();
            {
                int lo = g*16;
                const float4* srow = (const float4*)&psw[n*PSTR + hbase];
                float4 s0 = srow[0], s1 = srow[1], s2 = srow[2], s3 = srow[3];
                const float4* crow = (const float4*)&P[(lo + n)*SPSTR + DTR + NST];
                float4 c0 = crow[0], c1 = crow[1], c2 = crow[2], c3 = crow[3];
                float a0 = fmaf(s0.w, c0.w, fmaf(s0.z, c0.z, fmaf(s0.y, c0.y, s0.x*c0.x)));
                float a1 = fmaf(s1.w, c1.w, fmaf(s1.z, c1.z, fmaf(s1.y, c1.y, s1.x*c1.x)));
                float a2 = fmaf(s2.w, c2.w, fmaf(s2.z, c2.z, fmaf(s2.y, c2.y, s2.x*c2.x)));
                float a3 = fmaf(s3.w, c3.w, fmaf(s3.z, c3.z, fmaf(s3.y, c3.y, s3.x*c3.x)));
                float ssum = (a0 + a1) + (a2 + a3);
                float2 gg = *(const float2*)&sgg[(lo + n)*32 + hw*2];
                su2[(lo + n)*16 + hw] = fmaf(ssum, gg.x, gg.y);
            }
            __syncwarp();
        }
        __syncthreads();

        // coalesced writeback
        {
            float4 v = *(const float4*)&su2[rl*16 + rq*4];
            *(float4*)(g_ymod + (size_t)(blbase + cc*SCH + rl)*DI + d0 + rq*4) = v;
        }
    }
}

// ---------------- Residual add + LayerNorm: warp-per-row, float4 ----------------
__global__ void __launch_bounds__(512)
ln_kernel(const float* __restrict__ gamma,
          const float* __restrict__ beta) {
    int wid  = threadIdx.x >> 5;
    int lane = threadIdx.x & 31;
    int bl   = blockIdx.x * 16 + wid;
    int col  = lane * 8;

    const float4* o4 = (const float4*)(g_out2 + (size_t)bl*DM + col);
    const float4* h4 = (const float4*)(g_h    + (size_t)bl*DM + col);
    float t[8];
    float4 a = o4[0], b = h4[0];
    t[0]=a.x+b.x; t[1]=a.y+b.y; t[2]=a.z+b.z; t[3]=a.w+b.w;
    a = o4[1]; b = h4[1];
    t[4]=a.x+b.x; t[5]=a.y+b.y; t[6]=a.z+b.z; t[7]=a.w+b.w;

    float v1 = 0.f, v2 = 0.f;
#pragma unroll
    for (int i = 0; i < 8; i++) { v1 += t[i]; v2 = fmaf(t[i], t[i], v2); }
#pragma unroll
    for (int o = 16; o > 0; o >>= 1) {
        v1 += __shfl_xor_sync(0xffffffffu, v1, o);
        v2 += __shfl_xor_sync(0xffffffffu, v2, o);
    }
    float mean = v1 * (1.f/DM);
    float var  = v2 * (1.f/DM) - mean*mean;
    float rs = rsqrtf(var + 1e-5f);

    float4 g0 = *(const float4*)(gamma + col);
    float4 g1 = *(const float4*)(gamma + col + 4);
    float4 b0 = *(const float4*)(beta  + col);
    float4 b1 = *(const float4*)(beta  + col + 4);

    float4 r0, r1;
    r0.x = (t[0]-mean)*rs*g0.x + b0.x;
    r0.y = (t[1]-mean)*rs*g0.y + b0.y;
    r0.z = (t[2]-mean)*rs*g0.z + b0.z;
    r0.w = (t[3]-mean)*rs*g0.w + b0.w;
    r1.x = (t[4]-mean)*rs*g1.x + b1.x;
    r1.y = (t[5]-mean)*rs*g1.y + b1.y;
    r1.z = (t[6]-mean)*rs*g1.z + b1.z;
    r1.w = (t[7]-mean)*rs*g1.w + b1.w;

    float4* out4 = (float4*)(g_h + (size_t)bl*DM + col);
    out4[0] = r0;
    out4[1] = r1;
}

// ---------------- Mean pool ----------------
__global__ void pool_kernel() {
    int b = blockIdx.x;
    int m = threadIdx.x;
    float s = 0.f;
    for (int l = 0; l < LSEQ; l++)
        s += g_h[(size_t)((b << 10) + l)*DM + m];
    g_pooled[b*DM + m] = s * (1.f/LSEQ);
}

// ---------------- Decoder ----------------
__global__ void dec_kernel(const float* __restrict__ w,
                           const float* __restrict__ bb,
                           float* __restrict__ out) {
    int i = threadIdx.x;
    if (i < BSZ*10) {
        int b = i / 10, o = i % 10;
        float acc = bb[o];
#pragma unroll 8
        for (int m = 0; m < DM; m++)
            acc = fmaf(g_pooled[b*DM + m], w[m*10 + o], acc);
        out[i] = acc;
    }
}

// ---------------- Launch ----------------
extern "C" void kernel_launch(void* const* d_in, const int* in_sizes, int n_in,
                              void* d_out, int out_size) {
    const float* x         = (const float*)d_in[0];
    const float* enc_w     = (const float*)d_in[1];
    const float* enc_b     = (const float*)d_in[2];
    const float* in_proj_w = (const float*)d_in[3];
    const float* conv_w    = (const float*)d_in[4];
    const float* conv_b    = (const float*)d_in[5];
    const float* x_proj_w  = (const float*)d_in[6];
    const float* dt_w      = (const float*)d_in[7];
    const float* dt_b      = (const float*)d_in[8];
    const float* A_log     = (const float*)d_in[9];
    const float* Dv        = (const float*)d_in[10];
    const float* out_proj_w= (const float*)d_in[11];
    const float* ln_g      = (const float*)d_in[12];
    const float* ln_b      = (const float*)d_in[13];
    const float* dec_w     = (const float*)d_in[14];
    const float* dec_b     = (const float*)d_in[15];

    float *p_h, *p_xz, *p_proj, *p_ymod, *p_out2;
    cudaGetSymbolAddress((void**)&p_h,    g_h);
    cudaGetSymbolAddress((void**)&p_xz,   g_xz);
    cudaGetSymbolAddress((void**)&p_proj, g_proj);
    cudaGetSymbolAddress((void**)&p_ymod, g_ymod);
    cudaGetSymbolAddress((void**)&p_out2, g_out2);

    enc_kernel<<<MROWS, DM>>>(x, enc_w, enc_b);

    for (int i = 0; i < NL; i++) {
        gemm_tf32_cp<128><<<dim3((2*DI)/64, MROWS/128), 256>>>(
            p_h, in_proj_w + (size_t)i*DM*2*DI, p_xz, MROWS, 2*DI, DM);

        xproj_conv_gemm<<<dim3(1, MROWS/64), 256>>>(
            p_xz, x_proj_w + (size_t)i*DI*PROJC, p_proj,
            conv_w + (size_t)i*DI*4, conv_b + (size_t)i*DI);

        scan_kernel<<<BSZ*32, 256>>>(A_log + (size_t)i*DI*NST, Dv + (size_t)i*DI,
                                     dt_w + (size_t)i*DTR*DI, dt_b + (size_t)i*DI,
                                     conv_w + (size_t)i*DI*4, conv_b + (size_t)i*DI);

        gemm_tf32_cp<128><<<dim3(DM/64, MROWS/128), 256>>>(
            p_ymod, out_proj_w + (size_t)i*DI*DM, p_out2, MROWS, DM, DI);

        ln_kernel<<<MROWS/16, 512>>>(ln_g + (size_t)i*DM, ln_b + (size_t)i*DM);
    }

    pool_kernel<<<BSZ, DM>>>();
    dec_kernel<<<1, 128>>>(dec_w, dec_b, (float*)d_out);
}

// round 16
// speedup vs baseline: 1.0222x; 1.0222x over previous
#include <cuda_runtime.h>
#include <cuda_bf16.h>
#include <math.h>

// ---------------- Problem dims ----------------
#define NL    8
#define BSZ   8
#define LSEQ  1024
#define DM    256
#define DI    512
#define NST   16
#define DTR   16
#define PROJC 48
#define MROWS (BSZ*LSEQ)  // 8192

// ---------------- Device scratch ----------------
__device__ float g_h   [MROWS*DM];
__device__ float g_xz  [MROWS*2*DI];
__device__ float g_proj[MROWS*PROJC];
__device__ float g_ymod[MROWS*DI];
__device__ float g_out2[MROWS*DM];
__device__ float g_pooled[BSZ*DM];

// ---------------- helpers ----------------
__device__ __forceinline__ void mma_tf32(float& d0, float& d1, float& d2, float& d3,
                                         unsigned a0, unsigned a1, unsigned a2, unsigned a3,
                                         unsigned b0, unsigned b1) {
    asm volatile(
        "mma.sync.aligned.m16n8k8.row.col.f32.tf32.tf32.f32 "
        "{%0,%1,%2,%3}, {%4,%5,%6,%7}, {%8,%9}, {%0,%1,%2,%3};\n"
        : "+f"(d0), "+f"(d1), "+f"(d2), "+f"(d3)
        : "r"(a0), "r"(a1), "r"(a2), "r"(a3), "r"(b0), "r"(b1));
}
__device__ __forceinline__ void cp16(unsigned dst, const void* src) {
    asm volatile("cp.async.cg.shared.global [%0], [%1], 16;\n" :: "r"(dst), "l"(src));
}
__device__ __forceinline__ void cp_commit() { asm volatile("cp.async.commit_group;\n"); }
__device__ __forceinline__ void cp_wait0()  { asm volatile("cp.async.wait_group 0;\n"); }
__device__ __forceinline__ void cp_wait1()  { asm volatile("cp.async.wait_group 1;\n"); }
__device__ __forceinline__ void cp_wait2()  { asm volatile("cp.async.wait_group 2;\n"); }

// ---------------- Encoder ----------------
__global__ void enc_kernel(const float* __restrict__ x,
                           const float* __restrict__ w,
                           const float* __restrict__ bb) {
    int bl = blockIdx.x;
    int m  = threadIdx.x;
    int b = bl >> 10, l = bl & 1023;
    float acc = bb[m];
#pragma unroll
    for (int c = 0; c < 3; c++)
        acc = fmaf(x[(b*3 + c)*LSEQ + l], w[c*DM + m], acc);
    g_h[bl*DM + m] = acc;
}

// ---------------- TF32 GEMM 128x128x16, 3-stage (in_proj) ----------------
// N%128==0, M%128==0, K%16==0. fp32 bits fed as tf32 (RZ).
#define ASTR 20
#define BSTR2 136
__global__ void __launch_bounds__(256, 2)
gemm_tf32_n128(const float* __restrict__ A,
               const float* __restrict__ B,
               float* __restrict__ C,
               int M, int N, int K) {
    __shared__ unsigned As[3][128*ASTR];   // 30.7 KB
    __shared__ unsigned Bs[3][16*BSTR2];   // 26.1 KB

    const int tid  = threadIdx.x;
    const int lane = tid & 31;
    const int wid  = tid >> 5;
    const int wm   = wid & 3;
    const int wn   = wid >> 2;
    const int m0   = blockIdx.y * 128;
    const int n0   = blockIdx.x * 128;
    const int r = lane >> 2;
    const int c = lane & 3;

    unsigned aBase[3], bBase[3];
#pragma unroll
    for (int s = 0; s < 3; s++) {
        aBase[s] = (unsigned)__cvta_generic_to_shared(&As[s][0]);
        bBase[s] = (unsigned)__cvta_generic_to_shared(&Bs[s][0]);
    }

    auto loadTile = [&](int t, int s) {
        int k0 = t * 16;
#pragma unroll
        for (int j = 0; j < 2; j++) {
            int slot = j*256 + tid;
            int row = slot >> 2, kq = slot & 3;
            cp16(aBase[s] + (row*ASTR + kq*4)*4,
                 A + (size_t)(m0 + row)*K + k0 + kq*4);
        }
#pragma unroll
        for (int j = 0; j < 2; j++) {
            int slot = j*256 + tid;
            int row = slot >> 5, nq = slot & 31;
            cp16(bBase[s] + (row*BSTR2 + nq*4)*4,
                 B + (size_t)(k0 + row)*N + n0 + nq*4);
        }
        cp_commit();
    };

    float acc[2][8][4] = {};
    const int T = K >> 4;

    loadTile(0, 0); loadTile(1, 1);

    for (int t = 0; t < T; t++) {
        int cur = t % 3;
        cp_wait1();
        __syncthreads();
        if (t + 2 < T) loadTile(t + 2, (t + 2) % 3);
        else           cp_commit();

        const unsigned* Ab = As[cur];
        const unsigned* Bb = Bs[cur];
#pragma unroll
        for (int kk = 0; kk < 16; kk += 8) {
            unsigned af[2][4], bf[8][2];
#pragma unroll
            for (int am = 0; am < 2; am++) {
                int mrow = wm*32 + am*16;
                af[am][0] = Ab[(mrow + r    )*ASTR + kk + c    ];
                af[am][1] = Ab[(mrow + r + 8)*ASTR + kk + c    ];
                af[am][2] = Ab[(mrow + r    )*ASTR + kk + c + 4];
                af[am][3] = Ab[(mrow + r + 8)*ASTR + kk + c + 4];
            }
#pragma unroll
            for (int bn = 0; bn < 8; bn++) {
                int ncol = wn*64 + bn*8 + r;
                bf[bn][0] = Bb[(kk + c    )*BSTR2 + ncol];
                bf[bn][1] = Bb[(kk + c + 4)*BSTR2 + ncol];
            }
#pragma unroll
            for (int am = 0; am < 2; am++)
#pragma unroll
                for (int bn = 0; bn < 8; bn++)
                    mma_tf32(acc[am][bn][0], acc[am][bn][1], acc[am][bn][2], acc[am][bn][3],
                             af[am][0], af[am][1], af[am][2], af[am][3],
                             bf[bn][0], bf[bn][1]);
        }
    }

#pragma unroll
    for (int am = 0; am < 2; am++) {
#pragma unroll
        for (int bn = 0; bn < 8; bn++) {
            int m = m0 + wm*32 + am*16 + r;
            int n = n0 + wn*64 + bn*8 + 2*c;
            *(float2*)(C + (size_t)m*N + n)       = make_float2(acc[am][bn][0], acc[am][bn][1]);
            *(float2*)(C + (size_t)(m + 8)*N + n) = make_float2(acc[am][bn][2], acc[am][bn][3]);
        }
    }
}

// ---------------- TF32 GEMM BMx64x16, 4-stage (out_proj, optional residual) -------
#define BSTR 72
template<int BM, int RES>
__global__ void __launch_bounds__(256, 2)
gemm_tf32_cp(const float* __restrict__ A,
             const float* __restrict__ B,
             float* __restrict__ C,
             const float* __restrict__ Rr,
             int M, int N, int K) {
    constexpr int AM = BM / 64;
    __shared__ unsigned As[4][BM*ASTR];
    __shared__ unsigned Bs[4][16*BSTR];

    const int tid  = threadIdx.x;
    const int lane = tid & 31;
    const int wid  = tid >> 5;
    const int wm   = wid & 3;
    const int wn   = wid >> 2;
    const int m0   = blockIdx.y * BM;
    const int n0   = blockIdx.x * 64;
    const int r = lane >> 2;
    const int c = lane & 3;

    const int bRow = tid >> 4;
    const int bNq  = tid & 15;
    const bool bOk = (n0 + bNq*4 + 3) < N;

    unsigned aBase[4], bBase[4];
#pragma unroll
    for (int s = 0; s < 4; s++) {
        aBase[s] = (unsigned)__cvta_generic_to_shared(&As[s][0]);
        bBase[s] = (unsigned)__cvta_generic_to_shared(&Bs[s][0]);
    }

    auto loadTile = [&](int t, int s) {
        int k0 = t * 16;
#pragma unroll
        for (int j = 0; j < AM; j++) {
            int slot = j*256 + tid;
            int row = slot >> 2, kq = slot & 3;
            cp16(aBase[s] + (row*ASTR + kq*4)*4,
                 A + (size_t)(m0 + row)*K + k0 + kq*4);
        }
        if (bOk)
            cp16(bBase[s] + (bRow*BSTR + bNq*4)*4,
                 B + (size_t)(k0 + bRow)*N + n0 + bNq*4);
        cp_commit();
    };

    float acc[AM][4][4] = {};
    const int T = K >> 4;

    loadTile(0, 0); loadTile(1, 1); loadTile(2, 2);

    for (int t = 0; t < T; t++) {
        int cur = t & 3;
        cp_wait2();
        __syncthreads();
        if (t + 3 < T) loadTile(t + 3, (t + 3) & 3);
        else           cp_commit();

        const unsigned* Ab = As[cur];
        const unsigned* Bb = Bs[cur];
#pragma unroll
        for (int kk = 0; kk < 16; kk += 8) {
            unsigned af[AM][4], bf[4][2];
#pragma unroll
            for (int am = 0; am < AM; am++) {
                int mrow = wm*(BM/4) + am*16;
                af[am][0] = Ab[(mrow + r    )*ASTR + kk + c    ];
                af[am][1] = Ab[(mrow + r + 8)*ASTR + kk + c    ];
                af[am][2] = Ab[(mrow + r    )*ASTR + kk + c + 4];
                af[am][3] = Ab[(mrow + r + 8)*ASTR + kk + c + 4];
            }
#pragma unroll
            for (int bn = 0; bn < 4; bn++) {
                int ncol = wn*32 + bn*8 + r;
                bf[bn][0] = Bb[(kk + c    )*BSTR + ncol];
                bf[bn][1] = Bb[(kk + c + 4)*BSTR + ncol];
            }
#pragma unroll
            for (int am = 0; am < AM; am++)
#pragma unroll
                for (int bn = 0; bn < 4; bn++)
                    mma_tf32(acc[am][bn][0], acc[am][bn][1], acc[am][bn][2], acc[am][bn][3],
                             af[am][0], af[am][1], af[am][2], af[am][3],
                             bf[bn][0], bf[bn][1]);
        }
    }

#pragma unroll
    for (int am = 0; am < AM; am++) {
#pragma unroll
        for (int bn = 0; bn < 4; bn++) {
            int m = m0 + wm*(BM/4) + am*16 + r;
            int n = n0 + wn*32 + bn*8 + 2*c;
            if (n + 1 < N) {
                float2 v0 = make_float2(acc[am][bn][0], acc[am][bn][1]);
                float2 v1 = make_float2(acc[am][bn][2], acc[am][bn][3]);
                if (RES) {
                    float2 r0 = *(const float2*)(Rr + (size_t)m*N + n);
                    float2 r1 = *(const float2*)(Rr + (size_t)(m + 8)*N + n);
                    v0.x += r0.x; v0.y += r0.y;
                    v1.x += r1.x; v1.y += r1.y;
                }
                *(float2*)(C + (size_t)m*N + n)       = v0;
                *(float2*)(C + (size_t)(m + 8)*N + n) = v1;
            } else if (n < N) {
                C[(size_t)m*N + n]       = acc[am][bn][0];
                C[(size_t)(m + 8)*N + n] = acc[am][bn][2];
            }
        }
    }
}

// ---------------- x_proj GEMM with fused conv+SiLU on the A path ----------------
#define RSTR 20
__global__ void __launch_bounds__(256)
xproj_conv_gemm(const float* __restrict__ xz,
                const float* __restrict__ W,
                float* __restrict__ Cout,
                const float* __restrict__ cw,
                const float* __restrict__ cb) {
    __shared__ unsigned As[64*RSTR];
    __shared__ float    Raw[3][67*RSTR];
    __shared__ unsigned Bs[3][16*BSTR];
    __shared__ float    scw[DI*4];
    __shared__ float    scb[DI];

    const int tid  = threadIdx.x;
    const int lane = tid & 31;
    const int wid  = tid >> 5;
    const int wm   = wid & 3;
    const int wn   = wid >> 2;
    const int m0   = blockIdx.y * 64;
    const int r = lane >> 2;
    const int c = lane & 3;

    for (int i = tid; i < 3*16*BSTR; i += 256) (&Bs[0][0])[i] = 0u;
    for (int i = tid; i < DI*4; i += 256) scw[i] = cw[i];
    for (int i = tid; i < DI;   i += 256) scb[i] = cb[i];
    const bool hz = (m0 & 1023) == 0;
    if (hz) {
#pragma unroll
        for (int s = 0; s < 3; s++)
            if (tid < 48) Raw[s][(tid >> 4)*RSTR + (tid & 15)] = 0.f;
    }
    __syncthreads();

    const int i1 = tid >> 2, q1 = tid & 3;
    const int bRow = tid >> 4;
    const int bNq  = tid & 15;
    const bool bOk = bNq < 12;

    unsigned rawB[3], bsB[3];
#pragma unroll
    for (int s = 0; s < 3; s++) {
        rawB[s] = (unsigned)__cvta_generic_to_shared(&Raw[s][0]);
        bsB[s]  = (unsigned)__cvta_generic_to_shared(&Bs[s][0]);
    }

    auto loadT = [&](int t, int s) {
        int k0 = t * 16;
        if (!hz || i1 >= 3)
            cp16(rawB[s] + (i1*RSTR + q1*4)*4,
                 xz + (size_t)(m0 - 3 + i1)*(2*DI) + k0 + q1*4);
        if (tid < 12) {
            int i2 = 64 + (tid >> 2);
            cp16(rawB[s] + (i2*RSTR + (tid & 3)*4)*4,
                 xz + (size_t)(m0 - 3 + i2)*(2*DI) + k0 + (tid & 3)*4);
        }
        if (bOk)
            cp16(bsB[s] + (bRow*BSTR + bNq*4)*4,
                 W + (size_t)(k0 + bRow)*PROJC + bNq*4);
        cp_commit();
    };

    float acc[4][4] = {};
    const int T = DI >> 4;

    loadT(0, 0); loadT(1, 1);

    for (int t = 0; t < T; t++) {
        int cur = t % 3;
        cp_wait1();
        __syncthreads();
        if (t + 2 < T) loadT(t + 2, (t + 2) % 3);
        else           cp_commit();

        {
            const float* R = Raw[cur];
            int row = tid >> 2;
            int cb4 = (tid & 3) * 4;
#pragma unroll
            for (int j = 0; j < 4; j++) {
                int cc = cb4 + j;
                int d  = t*16 + cc;
                float a = scb[d];
#pragma unroll
                for (int k = 0; k < 4; k++)
                    a = fmaf(R[(row + k)*RSTR + cc], scw[d*4 + k], a);
                a = a / (1.f + __expf(-a));
                As[row*RSTR + cc] = __float_as_uint(a);
            }
        }
        __syncthreads();

        const unsigned* Bb = Bs[cur];
#pragma unroll
        for (int kk = 0; kk < 16; kk += 8) {
            unsigned af[4], bf[4][2];
            {
                int mrow = wm*16;
                af[0] = As[(mrow + r    )*RSTR + kk + c    ];
                af[1] = As[(mrow + r + 8)*RSTR + kk + c    ];
                af[2] = As[(mrow + r    )*RSTR + kk + c + 4];
                af[3] = As[(mrow + r + 8)*RSTR + kk + c + 4];
            }
#pragma unroll
            for (int bn = 0; bn < 4; bn++) {
                int ncol = wn*32 + bn*8 + r;
                bf[bn][0] = Bb[(kk + c    )*BSTR + ncol];
                bf[bn][1] = Bb[(kk + c + 4)*BSTR + ncol];
            }
#pragma unroll
            for (int bn = 0; bn < 4; bn++)
                mma_tf32(acc[bn][0], acc[bn][1], acc[bn][2], acc[bn][3],
                         af[0], af[1], af[2], af[3],
                         bf[bn][0], bf[bn][1]);
        }
    }

#pragma unroll
    for (int bn = 0; bn < 4; bn++) {
        int m = m0 + wm*16 + r;
        int n = wn*32 + bn*8 + 2*c;
        if (n + 1 < PROJC) {
            *(float2*)(Cout + (size_t)m*PROJC + n)       = make_float2(acc[bn][0], acc[bn][1]);
            *(float2*)(Cout + (size_t)(m + 8)*PROJC + n) = make_float2(acc[bn][2], acc[bn][3]);
        } else if (n < PROJC) {
            Cout[(size_t)m*PROJC + n]       = acc[bn][0];
            Cout[(size_t)(m + 8)*PROJC + n] = acc[bn][2];
        }
    }
}

// ---------------- Fused conv + dt + scan, transpose-reduce (R14 structure) --------
#define SCH 64
#define SPSTR 52
#define PSTR 36
__global__ void __launch_bounds__(256)
scan_kernel(const float* __restrict__ A_log,
            const float* __restrict__ Dv,
            const float* __restrict__ dtw,
            const float* __restrict__ dtb,
            const float* __restrict__ cw,
            const float* __restrict__ cb) {
    __shared__ float sp[2][SCH*SPSTR];
    __shared__ float rx[2][67*16];
    __shared__ float sz[2][SCH*16];
    __shared__ float su2[SCH*16];
    __shared__ float sgg[SCH*32];
    __shared__ float psh[8*16*PSTR];
    __shared__ float sDv[16];

    const int b  = blockIdx.x >> 5;
    const int d0 = (blockIdx.x & 31) * 16;
    const int tid = threadIdx.x;
    const int hw = tid >> 4;
    const int n  = tid & 15;
    const int lane = tid & 31;
    const int wid  = tid >> 5;
    const int d  = d0 + hw;
    const int hbase = lane & 16;
    const int blbase = b << 10;

    const int rl = tid >> 2;
    const int rq = tid & 3;

    const int ccol = (tid & 3) * 4;
    float wv[4][4], bv[4];
#pragma unroll
    for (int j = 0; j < 4; j++) {
        bv[j] = cb[d0 + ccol + j];
#pragma unroll
        for (int k = 0; k < 4; k++)
            wv[j][k] = cw[(d0 + ccol + j)*4 + k];
    }
    if (tid < 16) sDv[tid] = Dv[d0 + tid];
    if (tid < 48) rx[0][tid] = 0.f;

    unsigned spB[2], rxB[2], szB[2];
#pragma unroll
    for (int s = 0; s < 2; s++) {
        spB[s] = (unsigned)__cvta_generic_to_shared(&sp[s][0]);
        rxB[s] = (unsigned)__cvta_generic_to_shared(&rx[s][0]);
        szB[s] = (unsigned)__cvta_generic_to_shared(&sz[s][0]);
    }

    auto loadChunk = [&](int c0, int buf) {
        cp16(rxB[buf] + (rl*16 + rq*4)*4,
             g_xz + (size_t)(blbase + c0 - 3 + rl)*(2*DI) + d0 + rq*4);
        if (tid < 12) {
            int i2 = 64 + (tid >> 2);
            cp16(rxB[buf] + (i2*16 + (tid & 3)*4)*4,
                 g_xz + (size_t)(blbase + c0 - 3 + i2)*(2*DI) + d0 + (tid & 3)*4);
        }
        cp16(szB[buf] + (rl*16 + rq*4)*4,
             g_xz + (size_t)(blbase + c0 + rl)*(2*DI) + DI + d0 + rq*4);
#pragma unroll
        for (int k = 0; k < 3; k++) {
            int s = tid + k*256;
            int l = s / 12, q = s - l*12;
            cp16(spB[buf] + (l*SPSTR + q*4)*4,
                 g_proj + (size_t)(blbase + c0 + l)*PROJC + q*4);
        }
        cp_commit();
    };
    auto loadChunk0 = [&]() {
        if (rl >= 3)
            cp16(rxB[0] + (rl*16 + rq*4)*4,
                 g_xz + (size_t)(blbase - 3 + rl)*(2*DI) + d0 + rq*4);
        if (tid < 12) {
            int i2 = 64 + (tid >> 2);
            cp16(rxB[0] + (i2*16 + (tid & 3)*4)*4,
                 g_xz + (size_t)(blbase - 3 + i2)*(2*DI) + d0 + (tid & 3)*4);
        }
        cp16(szB[0] + (rl*16 + rq*4)*4,
             g_xz + (size_t)(blbase + rl)*(2*DI) + DI + d0 + rq*4);
#pragma unroll
        for (int k = 0; k < 3; k++) {
            int s = tid + k*256;
            int l = s / 12, q = s - l*12;
            cp16(spB[0] + (l*SPSTR + q*4)*4,
                 g_proj + (size_t)(blbase + l)*PROJC + q*4);
        }
        cp_commit();
    };

    float wdt[DTR];
#pragma unroll
    for (int r = 0; r < DTR; r++) wdt[r] = dtw[r*DI + d];
    const float dtbv = dtb[d];
    const float Ad = -__expf(A_log[d*NST + n]);
    float state = 0.f;

    float* psw = &psh[wid*16*PSTR];

    loadChunk0();

    for (int cc = 0; cc < LSEQ/SCH; cc++) {
        int buf = cc & 1;
        if (cc + 1 < LSEQ/SCH) { loadChunk((cc+1)*SCH, buf ^ 1); cp_wait1(); }
        else                   { cp_wait0(); }
        __syncthreads();

        const float* P = sp[buf];
        const float* X = rx[buf];
        const float* Z = sz[buf];

        float dtv4[4];
#pragma unroll
        for (int j = 0; j < 4; j++) {
            float a = dtbv;
            const float* row = &P[(j*16 + n)*SPSTR];
#pragma unroll
            for (int r = 0; r < DTR; r++) a = fmaf(row[r], wdt[r], a);
            dtv4[j] = (a > 20.f) ? a : __logf(1.f + __expf(a));
        }

#pragma unroll
        for (int j = 0; j < 4; j++) {
            int c2 = ccol + j;
            float a = bv[j];
#pragma unroll
            for (int k = 0; k < 4; k++)
                a = fmaf(X[(rl + k)*16 + c2], wv[j][k], a);
            float u = a / (1.f + __expf(-a));
            su2[rl*16 + c2] = u;
            float zz = Z[rl*16 + c2];
            float gate = zz / (1.f + __expf(-zz));
            sgg[rl*32 + c2*2    ] = gate;
            sgg[rl*32 + c2*2 + 1] = u * sDv[c2] * gate;
        }
        __syncthreads();

#pragma unroll
        for (int g = 0; g < SCH/16; g++) {
#pragma unroll
            for (int i = 0; i < 16; i++) {
                int l = g*16 + i;
                float dtv = __shfl_sync(0xffffffffu, dtv4[l >> 4], hbase + (l & 15), 32);
                float uv  = su2[l*16 + hw];
                float Bv  = P[l*SPSTR + DTR + n];
                float Cv  = P[l*SPSTR + DTR + NST + n];
                state = fmaf(__expf(dtv*Ad), state, dtv*uv*Bv);
                psw[i*PSTR + lane] = state * Cv;
            }
            __syncwarp();
            {
                int lo = g*16;
                const float4* row = (const float4*)&psw[n*PSTR + hbase];
                float4 v0 = row[0], v1 = row[1], v2 = row[2], v3 = row[3];
                float s = (((v0.x+v0.y)+(v0.z+v0.w)) + ((v1.x+v1.y)+(v1.z+v1.w)))
                        + (((v2.x+v2.y)+(v2.z+v2.w)) + ((v3.x+v3.y)+(v3.z+v3.w)));
                float2 gg = *(const float2*)&sgg[(lo + n)*32 + hw*2];
                su2[(lo + n)*16 + hw] = fmaf(s, gg.x, gg.y);
            }
            __syncwarp();
        }
        __syncthreads();

        {
            float4 v = *(const float4*)&su2[rl*16 + rq*4];
            *(float4*)(g_ymod + (size_t)(blbase + cc*SCH + rl)*DI + d0 + rq*4) = v;
        }
    }
}

// ---------------- LayerNorm (input already has residual added) ----------------
__global__ void __launch_bounds__(512)
ln_kernel(const float* __restrict__ gamma,
          const float* __restrict__ beta) {
    int wid  = threadIdx.x >> 5;
    int lane = threadIdx.x & 31;
    int bl   = blockIdx.x * 16 + wid;
    int col  = lane * 8;

    const float4* o4 = (const float4*)(g_out2 + (size_t)bl*DM + col);
    float t[8];
    float4 a = o4[0];
    t[0]=a.x; t[1]=a.y; t[2]=a.z; t[3]=a.w;
    a = o4[1];
    t[4]=a.x; t[5]=a.y; t[6]=a.z; t[7]=a.w;

    float v1 = 0.f, v2 = 0.f;
#pragma unroll
    for (int i = 0; i < 8; i++) { v1 += t[i]; v2 = fmaf(t[i], t[i], v2); }
#pragma unroll
    for (int o = 16; o > 0; o >>= 1) {
        v1 += __shfl_xor_sync(0xffffffffu, v1, o);
        v2 += __shfl_xor_sync(0xffffffffu, v2, o);
    }
    float mean = v1 * (1.f/DM);
    float var  = v2 * (1.f/DM) - mean*mean;
    float rs = rsqrtf(var + 1e-5f);

    float4 g0 = *(const float4*)(gamma + col);
    float4 g1 = *(const float4*)(gamma + col + 4);
    float4 b0 = *(const float4*)(beta  + col);
    float4 b1 = *(const float4*)(beta  + col + 4);

    float4 r0, r1;
    r0.x = (t[0]-mean)*rs*g0.x + b0.x;
    r0.y = (t[1]-mean)*rs*g0.y + b0.y;
    r0.z = (t[2]-mean)*rs*g0.z + b0.z;
    r0.w = (t[3]-mean)*rs*g0.w + b0.w;
    r1.x = (t[4]-mean)*rs*g1.x + b1.x;
    r1.y = (t[5]-mean)*rs*g1.y + b1.y;
    r1.z = (t[6]-mean)*rs*g1.z + b1.z;
    r1.w = (t[7]-mean)*rs*g1.w + b1.w;

    float4* out4 = (float4*)(g_h + (size_t)bl*DM + col);
    out4[0] = r0;
    out4[1] = r1;
}

// ---------------- Mean pool ----------------
__global__ void pool_kernel() {
    int b = blockIdx.x;
    int m = threadIdx.x;
    float s = 0.f;
    for (int l = 0; l < LSEQ; l++)
        s += g_h[(size_t)((b << 10) + l)*DM + m];
    g_pooled[b*DM + m] = s * (1.f/LSEQ);
}

// ---------------- Decoder ----------------
__global__ void dec_kernel(const float* __restrict__ w,
                           const float* __restrict__ bb,
                           float* __restrict__ out) {
    int i = threadIdx.x;
    if (i < BSZ*10) {
        int b = i / 10, o = i % 10;
        float acc = bb[o];
#pragma unroll 8
        for (int m = 0; m < DM; m++)
            acc = fmaf(g_pooled[b*DM + m], w[m*10 + o], acc);
        out[i] = acc;
    }
}

// ---------------- Launch ----------------
extern "C" void kernel_launch(void* const* d_in, const int* in_sizes, int n_in,
                              void* d_out, int out_size) {
    const float* x         = (const float*)d_in[0];
    const float* enc_w     = (const float*)d_in[1];
    const float* enc_b     = (const float*)d_in[2];
    const float* in_proj_w = (const float*)d_in[3];
    const float* conv_w    = (const float*)d_in[4];
    const float* conv_b    = (const float*)d_in[5];
    const float* x_proj_w  = (const float*)d_in[6];
    const float* dt_w      = (const float*)d_in[7];
    const float* dt_b      = (const float*)d_in[8];
    const float* A_log     = (const float*)d_in[9];
    const float* Dv        = (const float*)d_in[10];
    const float* out_proj_w= (const float*)d_in[11];
    const float* ln_g      = (const float*)d_in[12];
    const float* ln_b      = (const float*)d_in[13];
    const float* dec_w     = (const float*)d_in[14];
    const float* dec_b     = (const float*)d_in[15];

    float *p_h, *p_xz, *p_proj, *p_ymod, *p_out2;
    cudaGetSymbolAddress((void**)&p_h,    g_h);
    cudaGetSymbolAddress((void**)&p_xz,   g_xz);
    cudaGetSymbolAddress((void**)&p_proj, g_proj);
    cudaGetSymbolAddress((void**)&p_ymod, g_ymod);
    cudaGetSymbolAddress((void**)&p_out2, g_out2);

    enc_kernel<<<MROWS, DM>>>(x, enc_w, enc_b);

    for (int i = 0; i < NL; i++) {
        // xz = h @ in_proj_w[i]   (8192x256 @ 256x1024)  BN=128 kernel
        gemm_tf32_n128<<<dim3((2*DI)/128, MROWS/128), 256>>>(
            p_h, in_proj_w + (size_t)i*DM*2*DI, p_xz, MROWS, 2*DI, DM);

        // proj = silu(conv(xz_x)) @ x_proj_w[i]
        xproj_conv_gemm<<<dim3(1, MROWS/64), 256>>>(
            p_xz, x_proj_w + (size_t)i*DI*PROJC, p_proj,
            conv_w + (size_t)i*DI*4, conv_b + (size_t)i*DI);

        // fused conv + dt + scan
        scan_kernel<<<BSZ*32, 256>>>(A_log + (size_t)i*DI*NST, Dv + (size_t)i*DI,
                                     dt_w + (size_t)i*DTR*DI, dt_b + (size_t)i*DI,
                                     conv_w + (size_t)i*DI*4, conv_b + (size_t)i*DI);

        // out2 = ymod @ out_proj_w[i] + h  (residual fused)
        gemm_tf32_cp<128,1><<<dim3(DM/64, MROWS/128), 256>>>(
            p_ymod, out_proj_w + (size_t)i*DI*DM, p_out2, p_h, MROWS, DM, DI);

        // h = layernorm(out2)
        ln_kernel<<<MROWS/16, 512>>>(ln_g + (size_t)i*DM, ln_b + (size_t)i*DM);
    }

    pool_kernel<<<BSZ, DM>>>();
    dec_kernel<<<1, 128>>>(dec_w, dec_b, (float*)d_out);
}

// round 17
// speedup vs baseline: 1.0376x; 1.0151x over previous
#include <cuda_runtime.h>
#include <cuda_bf16.h>
#include <math.h>

// ---------------- Problem dims ----------------
#define NL    8
#define BSZ   8
#define LSEQ  1024
#define DM    256
#define DI    512
#define NST   16
#define DTR   16
#define PROJC 48
#define MROWS (BSZ*LSEQ)  // 8192

// ---------------- Device scratch ----------------
__device__ float g_h   [MROWS*DM];
__device__ float g_xz  [MROWS*2*DI];
__device__ float g_proj[MROWS*PROJC];
__device__ float g_ymod[MROWS*DI];
__device__ float g_out2[MROWS*DM];
__device__ float g_pooled[BSZ*DM];

// ---------------- helpers ----------------
__device__ __forceinline__ void mma_tf32(float& d0, float& d1, float& d2, float& d3,
                                         unsigned a0, unsigned a1, unsigned a2, unsigned a3,
                                         unsigned b0, unsigned b1) {
    asm volatile(
        "mma.sync.aligned.m16n8k8.row.col.f32.tf32.tf32.f32 "
        "{%0,%1,%2,%3}, {%4,%5,%6,%7}, {%8,%9}, {%0,%1,%2,%3};\n"
        : "+f"(d0), "+f"(d1), "+f"(d2), "+f"(d3)
        : "r"(a0), "r"(a1), "r"(a2), "r"(a3), "r"(b0), "r"(b1));
}
__device__ __forceinline__ void cp16(unsigned dst, const void* src) {
    asm volatile("cp.async.cg.shared.global [%0], [%1], 16;\n" :: "r"(dst), "l"(src));
}
__device__ __forceinline__ void cp_commit() { asm volatile("cp.async.commit_group;\n"); }
__device__ __forceinline__ void cp_wait0()  { asm volatile("cp.async.wait_group 0;\n"); }
__device__ __forceinline__ void cp_wait1()  { asm volatile("cp.async.wait_group 1;\n"); }
__device__ __forceinline__ void cp_wait2()  { asm volatile("cp.async.wait_group 2;\n"); }

// ---------------- Encoder ----------------
__global__ void enc_kernel(const float* __restrict__ x,
                           const float* __restrict__ w,
                           const float* __restrict__ bb) {
    int bl = blockIdx.x;
    int m  = threadIdx.x;
    int b = bl >> 10, l = bl & 1023;
    float acc = bb[m];
#pragma unroll
    for (int c = 0; c < 3; c++)
        acc = fmaf(x[(b*3 + c)*LSEQ + l], w[c*DM + m], acc);
    g_h[bl*DM + m] = acc;
}

// ---------------- TF32 GEMM 128x128x16, 3-stage (in_proj) ----------------
#define ASTR 20
#define BSTR2 136
__global__ void __launch_bounds__(256, 2)
gemm_tf32_n128(const float* __restrict__ A,
               const float* __restrict__ B,
               float* __restrict__ C,
               int M, int N, int K) {
    __shared__ unsigned As[3][128*ASTR];
    __shared__ unsigned Bs[3][16*BSTR2];

    const int tid  = threadIdx.x;
    const int lane = tid & 31;
    const int wid  = tid >> 5;
    const int wm   = wid & 3;
    const int wn   = wid >> 2;
    const int m0   = blockIdx.y * 128;
    const int n0   = blockIdx.x * 128;
    const int r = lane >> 2;
    const int c = lane & 3;

    unsigned aBase[3], bBase[3];
#pragma unroll
    for (int s = 0; s < 3; s++) {
        aBase[s] = (unsigned)__cvta_generic_to_shared(&As[s][0]);
        bBase[s] = (unsigned)__cvta_generic_to_shared(&Bs[s][0]);
    }

    auto loadTile = [&](int t, int s) {
        int k0 = t * 16;
#pragma unroll
        for (int j = 0; j < 2; j++) {
            int slot = j*256 + tid;
            int row = slot >> 2, kq = slot & 3;
            cp16(aBase[s] + (row*ASTR + kq*4)*4,
                 A + (size_t)(m0 + row)*K + k0 + kq*4);
        }
#pragma unroll
        for (int j = 0; j < 2; j++) {
            int slot = j*256 + tid;
            int row = slot >> 5, nq = slot & 31;
            cp16(bBase[s] + (row*BSTR2 + nq*4)*4,
                 B + (size_t)(k0 + row)*N + n0 + nq*4);
        }
        cp_commit();
    };

    float acc[2][8][4] = {};
    const int T = K >> 4;

    loadTile(0, 0); loadTile(1, 1);

    for (int t = 0; t < T; t++) {
        int cur = t % 3;
        cp_wait1();
        __syncthreads();
        if (t + 2 < T) loadTile(t + 2, (t + 2) % 3);
        else           cp_commit();

        const unsigned* Ab = As[cur];
        const unsigned* Bb = Bs[cur];
#pragma unroll
        for (int kk = 0; kk < 16; kk += 8) {
            unsigned af[2][4], bf[8][2];
#pragma unroll
            for (int am = 0; am < 2; am++) {
                int mrow = wm*32 + am*16;
                af[am][0] = Ab[(mrow + r    )*ASTR + kk + c    ];
                af[am][1] = Ab[(mrow + r + 8)*ASTR + kk + c    ];
                af[am][2] = Ab[(mrow + r    )*ASTR + kk + c + 4];
                af[am][3] = Ab[(mrow + r + 8)*ASTR + kk + c + 4];
            }
#pragma unroll
            for (int bn = 0; bn < 8; bn++) {
                int ncol = wn*64 + bn*8 + r;
                bf[bn][0] = Bb[(kk + c    )*BSTR2 + ncol];
                bf[bn][1] = Bb[(kk + c + 4)*BSTR2 + ncol];
            }
#pragma unroll
            for (int am = 0; am < 2; am++)
#pragma unroll
                for (int bn = 0; bn < 8; bn++)
                    mma_tf32(acc[am][bn][0], acc[am][bn][1], acc[am][bn][2], acc[am][bn][3],
                             af[am][0], af[am][1], af[am][2], af[am][3],
                             bf[bn][0], bf[bn][1]);
        }
    }

#pragma unroll
    for (int am = 0; am < 2; am++) {
#pragma unroll
        for (int bn = 0; bn < 8; bn++) {
            int m = m0 + wm*32 + am*16 + r;
            int n = n0 + wn*64 + bn*8 + 2*c;
            *(float2*)(C + (size_t)m*N + n)       = make_float2(acc[am][bn][0], acc[am][bn][1]);
            *(float2*)(C + (size_t)(m + 8)*N + n) = make_float2(acc[am][bn][2], acc[am][bn][3]);
        }
    }
}

// ---------------- TF32 GEMM BMx64x16, 4-stage (out_proj, residual fused) ----------
#define BSTR 72
template<int BM, int RES>
__global__ void __launch_bounds__(256, 2)
gemm_tf32_cp(const float* __restrict__ A,
             const float* __restrict__ B,
             float* __restrict__ C,
             const float* __restrict__ Rr,
             int M, int N, int K) {
    constexpr int AM = BM / 64;
    __shared__ unsigned As[4][BM*ASTR];
    __shared__ unsigned Bs[4][16*BSTR];

    const int tid  = threadIdx.x;
    const int lane = tid & 31;
    const int wid  = tid >> 5;
    const int wm   = wid & 3;
    const int wn   = wid >> 2;
    const int m0   = blockIdx.y * BM;
    const int n0   = blockIdx.x * 64;
    const int r = lane >> 2;
    const int c = lane & 3;

    const int bRow = tid >> 4;
    const int bNq  = tid & 15;
    const bool bOk = (n0 + bNq*4 + 3) < N;

    unsigned aBase[4], bBase[4];
#pragma unroll
    for (int s = 0; s < 4; s++) {
        aBase[s] = (unsigned)__cvta_generic_to_shared(&As[s][0]);
        bBase[s] = (unsigned)__cvta_generic_to_shared(&Bs[s][0]);
    }

    auto loadTile = [&](int t, int s) {
        int k0 = t * 16;
#pragma unroll
        for (int j = 0; j < AM; j++) {
            int slot = j*256 + tid;
            int row = slot >> 2, kq = slot & 3;
            cp16(aBase[s] + (row*ASTR + kq*4)*4,
                 A + (size_t)(m0 + row)*K + k0 + kq*4);
        }
        if (bOk)
            cp16(bBase[s] + (bRow*BSTR + bNq*4)*4,
                 B + (size_t)(k0 + bRow)*N + n0 + bNq*4);
        cp_commit();
    };

    float acc[AM][4][4] = {};
    const int T = K >> 4;

    loadTile(0, 0); loadTile(1, 1); loadTile(2, 2);

    for (int t = 0; t < T; t++) {
        int cur = t & 3;
        cp_wait2();
        __syncthreads();
        if (t + 3 < T) loadTile(t + 3, (t + 3) & 3);
        else           cp_commit();

        const unsigned* Ab = As[cur];
        const unsigned* Bb = Bs[cur];
#pragma unroll
        for (int kk = 0; kk < 16; kk += 8) {
            unsigned af[AM][4], bf[4][2];
#pragma unroll
            for (int am = 0; am < AM; am++) {
                int mrow = wm*(BM/4) + am*16;
                af[am][0] = Ab[(mrow + r    )*ASTR + kk + c    ];
                af[am][1] = Ab[(mrow + r + 8)*ASTR + kk + c    ];
                af[am][2] = Ab[(mrow + r    )*ASTR + kk + c + 4];
                af[am][3] = Ab[(mrow + r + 8)*ASTR + kk + c + 4];
            }
#pragma unroll
            for (int bn = 0; bn < 4; bn++) {
                int ncol = wn*32 + bn*8 + r;
                bf[bn][0] = Bb[(kk + c    )*BSTR + ncol];
                bf[bn][1] = Bb[(kk + c + 4)*BSTR + ncol];
            }
#pragma unroll
            for (int am = 0; am < AM; am++)
#pragma unroll
                for (int bn = 0; bn < 4; bn++)
                    mma_tf32(acc[am][bn][0], acc[am][bn][1], acc[am][bn][2], acc[am][bn][3],
                             af[am][0], af[am][1], af[am][2], af[am][3],
                             bf[bn][0], bf[bn][1]);
        }
    }

#pragma unroll
    for (int am = 0; am < AM; am++) {
#pragma unroll
        for (int bn = 0; bn < 4; bn++) {
            int m = m0 + wm*(BM/4) + am*16 + r;
            int n = n0 + wn*32 + bn*8 + 2*c;
            if (n + 1 < N) {
                float2 v0 = make_float2(acc[am][bn][0], acc[am][bn][1]);
                float2 v1 = make_float2(acc[am][bn][2], acc[am][bn][3]);
                if (RES) {
                    float2 r0 = *(const float2*)(Rr + (size_t)m*N + n);
                    float2 r1 = *(const float2*)(Rr + (size_t)(m + 8)*N + n);
                    v0.x += r0.x; v0.y += r0.y;
                    v1.x += r1.x; v1.y += r1.y;
                }
                *(float2*)(C + (size_t)m*N + n)       = v0;
                *(float2*)(C + (size_t)(m + 8)*N + n) = v1;
            } else if (n < N) {
                C[(size_t)m*N + n]       = acc[am][bn][0];
                C[(size_t)(m + 8)*N + n] = acc[am][bn][2];
            }
        }
    }
}

// ---------------- x_proj GEMM with fused conv+SiLU on the A path ----------------
#define RSTR 20
__global__ void __launch_bounds__(256)
xproj_conv_gemm(const float* __restrict__ xz,
                const float* __restrict__ W,
                float* __restrict__ Cout,
                const float* __restrict__ cw,
                const float* __restrict__ cb) {
    __shared__ unsigned As[64*RSTR];
    __shared__ float    Raw[3][67*RSTR];
    __shared__ unsigned Bs[3][16*BSTR];
    __shared__ float    scw[DI*4];
    __shared__ float    scb[DI];

    const int tid  = threadIdx.x;
    const int lane = tid & 31;
    const int wid  = tid >> 5;
    const int wm   = wid & 3;
    const int wn   = wid >> 2;
    const int m0   = blockIdx.y * 64;
    const int r = lane >> 2;
    const int c = lane & 3;

    for (int i = tid; i < 3*16*BSTR; i += 256) (&Bs[0][0])[i] = 0u;
    for (int i = tid; i < DI*4; i += 256) scw[i] = cw[i];
    for (int i = tid; i < DI;   i += 256) scb[i] = cb[i];
    const bool hz = (m0 & 1023) == 0;
    if (hz) {
#pragma unroll
        for (int s = 0; s < 3; s++)
            if (tid < 48) Raw[s][(tid >> 4)*RSTR + (tid & 15)] = 0.f;
    }
    __syncthreads();

    const int i1 = tid >> 2, q1 = tid & 3;
    const int bRow = tid >> 4;
    const int bNq  = tid & 15;
    const bool bOk = bNq < 12;

    unsigned rawB[3], bsB[3];
#pragma unroll
    for (int s = 0; s < 3; s++) {
        rawB[s] = (unsigned)__cvta_generic_to_shared(&Raw[s][0]);
        bsB[s]  = (unsigned)__cvta_generic_to_shared(&Bs[s][0]);
    }

    auto loadT = [&](int t, int s) {
        int k0 = t * 16;
        if (!hz || i1 >= 3)
            cp16(rawB[s] + (i1*RSTR + q1*4)*4,
                 xz + (size_t)(m0 - 3 + i1)*(2*DI) + k0 + q1*4);
        if (tid < 12) {
            int i2 = 64 + (tid >> 2);
            cp16(rawB[s] + (i2*RSTR + (tid & 3)*4)*4,
                 xz + (size_t)(m0 - 3 + i2)*(2*DI) + k0 + (tid & 3)*4);
        }
        if (bOk)
            cp16(bsB[s] + (bRow*BSTR + bNq*4)*4,
                 W + (size_t)(k0 + bRow)*PROJC + bNq*4);
        cp_commit();
    };

    float acc[4][4] = {};
    const int T = DI >> 4;

    loadT(0, 0); loadT(1, 1);

    for (int t = 0; t < T; t++) {
        int cur = t % 3;
        cp_wait1();
        __syncthreads();
        if (t + 2 < T) loadT(t + 2, (t + 2) % 3);
        else           cp_commit();

        {
            const float* R = Raw[cur];
            int row = tid >> 2;
            int cb4 = (tid & 3) * 4;
#pragma unroll
            for (int j = 0; j < 4; j++) {
                int cc = cb4 + j;
                int d  = t*16 + cc;
                float a = scb[d];
#pragma unroll
                for (int k = 0; k < 4; k++)
                    a = fmaf(R[(row + k)*RSTR + cc], scw[d*4 + k], a);
                a = a / (1.f + __expf(-a));
                As[row*RSTR + cc] = __float_as_uint(a);
            }
        }
        __syncthreads();

        const unsigned* Bb = Bs[cur];
#pragma unroll
        for (int kk = 0; kk < 16; kk += 8) {
            unsigned af[4], bf[4][2];
            {
                int mrow = wm*16;
                af[0] = As[(mrow + r    )*RSTR + kk + c    ];
                af[1] = As[(mrow + r + 8)*RSTR + kk + c    ];
                af[2] = As[(mrow + r    )*RSTR + kk + c + 4];
                af[3] = As[(mrow + r + 8)*RSTR + kk + c + 4];
            }
#pragma unroll
            for (int bn = 0; bn < 4; bn++) {
                int ncol = wn*32 + bn*8 + r;
                bf[bn][0] = Bb[(kk + c    )*BSTR + ncol];
                bf[bn][1] = Bb[(kk + c + 4)*BSTR + ncol];
            }
#pragma unroll
            for (int bn = 0; bn < 4; bn++)
                mma_tf32(acc[bn][0], acc[bn][1], acc[bn][2], acc[bn][3],
                         af[0], af[1], af[2], af[3],
                         bf[bn][0], bf[bn][1]);
        }
    }

#pragma unroll
    for (int bn = 0; bn < 4; bn++) {
        int m = m0 + wm*16 + r;
        int n = wn*32 + bn*8 + 2*c;
        if (n + 1 < PROJC) {
            *(float2*)(Cout + (size_t)m*PROJC + n)       = make_float2(acc[bn][0], acc[bn][1]);
            *(float2*)(Cout + (size_t)(m + 8)*PROJC + n) = make_float2(acc[bn][2], acc[bn][3]);
        } else if (n < PROJC) {
            Cout[(size_t)m*PROJC + n]       = acc[bn][0];
            Cout[(size_t)(m + 8)*PROJC + n] = acc[bn][2];
        }
    }
}

// ---------------- Fused conv + dt + scan, transposed vectorized staging ----------
// Serial loop per 4 steps: 1 LDS.128 (u, bcast) + 2 LDS.128 (BC pairs) + 4 STS
// (vs 16 LSU ops before). Transposes built in the parallel convert phase.
#define SCH 64
#define SPSTR 52
#define PSTR 36
#define TSTR 68    // su2T stride (16B-aligned)
#define BCSTR 132  // sBCT stride (16B-aligned)
__global__ void __launch_bounds__(256)
scan_kernel(const float* __restrict__ A_log,
            const float* __restrict__ Dv,
            const float* __restrict__ dtw,
            const float* __restrict__ dtb,
            const float* __restrict__ cw,
            const float* __restrict__ cb) {
    __shared__ float sp[2][SCH*SPSTR];   // proj rows            26.6 KB
    __shared__ float rx[2][67*16];       // raw x + halo          8.6 KB
    __shared__ float sz[2][SCH*16];      // raw z                 8.2 KB
    __shared__ float su2T[16*TSTR];      // u transposed [hw][l]  4.4 KB
    __shared__ float sBCT[16*BCSTR];     // {B,C} pairs [n][2l]   8.4 KB
    __shared__ float sy[SCH*16];         // y output              4.1 KB
    __shared__ float sgg[SCH*32];        // gate, u*D*gate        8.2 KB
    __shared__ float psh[8*16*PSTR];     // state tile           18.4 KB
    __shared__ float sDv[16];

    const int b  = blockIdx.x >> 5;
    const int d0 = (blockIdx.x & 31) * 16;
    const int tid = threadIdx.x;
    const int hw = tid >> 4;
    const int n  = tid & 15;
    const int lane = tid & 31;
    const int wid  = tid >> 5;
    const int d  = d0 + hw;
    const int hbase = lane & 16;
    const int blbase = b << 10;

    const int rl = tid >> 2;
    const int rq = tid & 3;

    const int ccol = (tid & 3) * 4;
    float wv[4][4], bv[4];
#pragma unroll
    for (int j = 0; j < 4; j++) {
        bv[j] = cb[d0 + ccol + j];
#pragma unroll
        for (int k = 0; k < 4; k++)
            wv[j][k] = cw[(d0 + ccol + j)*4 + k];
    }
    if (tid < 16) sDv[tid] = Dv[d0 + tid];
    if (tid < 48) rx[0][tid] = 0.f;

    unsigned spB[2], rxB[2], szB[2];
#pragma unroll
    for (int s = 0; s < 2; s++) {
        spB[s] = (unsigned)__cvta_generic_to_shared(&sp[s][0]);
        rxB[s] = (unsigned)__cvta_generic_to_shared(&rx[s][0]);
        szB[s] = (unsigned)__cvta_generic_to_shared(&sz[s][0]);
    }

    auto loadChunk = [&](int c0, int buf) {
        cp16(rxB[buf] + (rl*16 + rq*4)*4,
             g_xz + (size_t)(blbase + c0 - 3 + rl)*(2*DI) + d0 + rq*4);
        if (tid < 12) {
            int i2 = 64 + (tid >> 2);
            cp16(rxB[buf] + (i2*16 + (tid & 3)*4)*4,
                 g_xz + (size_t)(blbase + c0 - 3 + i2)*(2*DI) + d0 + (tid & 3)*4);
        }
        cp16(szB[buf] + (rl*16 + rq*4)*4,
             g_xz + (size_t)(blbase + c0 + rl)*(2*DI) + DI + d0 + rq*4);
#pragma unroll
        for (int k = 0; k < 3; k++) {
            int s = tid + k*256;
            int l = s / 12, q = s - l*12;
            cp16(spB[buf] + (l*SPSTR + q*4)*4,
                 g_proj + (size_t)(blbase + c0 + l)*PROJC + q*4);
        }
        cp_commit();
    };
    auto loadChunk0 = [&]() {
        if (rl >= 3)
            cp16(rxB[0] + (rl*16 + rq*4)*4,
                 g_xz + (size_t)(blbase - 3 + rl)*(2*DI) + d0 + rq*4);
        if (tid < 12) {
            int i2 = 64 + (tid >> 2);
            cp16(rxB[0] + (i2*16 + (tid & 3)*4)*4,
                 g_xz + (size_t)(blbase - 3 + i2)*(2*DI) + d0 + (tid & 3)*4);
        }
        cp16(szB[0] + (rl*16 + rq*4)*4,
             g_xz + (size_t)(blbase + rl)*(2*DI) + DI + d0 + rq*4);
#pragma unroll
        for (int k = 0; k < 3; k++) {
            int s = tid + k*256;
            int l = s / 12, q = s - l*12;
            cp16(spB[0] + (l*SPSTR + q*4)*4,
                 g_proj + (size_t)(blbase + l)*PROJC + q*4);
        }
        cp_commit();
    };

    float wdt[DTR];
#pragma unroll
    for (int r = 0; r < DTR; r++) wdt[r] = dtw[r*DI + d];
    const float dtbv = dtb[d];
    const float Ad = -__expf(A_log[d*NST + n]);
    float state = 0.f;

    float* psw = &psh[wid*16*PSTR];

    loadChunk0();

    for (int cc = 0; cc < LSEQ/SCH; cc++) {
        int buf = cc & 1;
        if (cc + 1 < LSEQ/SCH) { loadChunk((cc+1)*SCH, buf ^ 1); cp_wait1(); }
        else                   { cp_wait0(); }
        __syncthreads();

        const float* P = sp[buf];
        const float* X = rx[buf];
        const float* Z = sz[buf];

        // dt for steps {j*16+n}
        float dtv4[4];
#pragma unroll
        for (int j = 0; j < 4; j++) {
            float a = dtbv;
            const float* row = &P[(j*16 + n)*SPSTR];
#pragma unroll
            for (int r = 0; r < DTR; r++) a = fmaf(row[r], wdt[r], a);
            dtv4[j] = (a > 20.f) ? a : __logf(1.f + __expf(a));
        }

        // convert: u -> su2T (transposed), gate pairs -> sgg
#pragma unroll
        for (int j = 0; j < 4; j++) {
            int c2 = ccol + j;
            float a = bv[j];
#pragma unroll
            for (int k = 0; k < 4; k++)
                a = fmaf(X[(rl + k)*16 + c2], wv[j][k], a);
            float u = a / (1.f + __expf(-a));
            su2T[c2*TSTR + rl] = u;
            float zz = Z[rl*16 + c2];
            float gate = zz / (1.f + __expf(-zz));
            sgg[rl*32 + c2*2    ] = gate;
            sgg[rl*32 + c2*2 + 1] = u * sDv[c2] * gate;
        }
        // BC transpose staging: sBCT[n][2l] = {B, C}
#pragma unroll
        for (int k2 = 0; k2 < 4; k2++) {
            int t2 = tid + k2*256;
            int l  = t2 >> 4;
            int n2 = t2 & 15;
            float Bv = P[l*SPSTR + DTR + n2];
            float Cv = P[l*SPSTR + DTR + NST + n2];
            *(float2*)&sBCT[n2*BCSTR + l*2] = make_float2(Bv, Cv);
        }
        __syncthreads();

        // serial loop: 16-step groups, 4-step vector fetch
#pragma unroll
        for (int g = 0; g < SCH/16; g++) {
#pragma unroll
            for (int q = 0; q < 4; q++) {
                int l0 = g*16 + q*4;
                float4 uq  = *(const float4*)&su2T[hw*TSTR + l0];
                float4 bc0 = *(const float4*)&sBCT[n*BCSTR + l0*2];
                float4 bc1 = *(const float4*)&sBCT[n*BCSTR + l0*2 + 4];
                float dtv;
                dtv = __shfl_sync(0xffffffffu, dtv4[g], hbase + ((l0+0) & 15), 32);
                state = fmaf(__expf(dtv*Ad), state, dtv*uq.x*bc0.x);
                psw[(q*4+0)*PSTR + lane] = state * bc0.y;
                dtv = __shfl_sync(0xffffffffu, dtv4[g], hbase + ((l0+1) & 15), 32);
                state = fmaf(__expf(dtv*Ad), state, dtv*uq.y*bc0.z);
                psw[(q*4+1)*PSTR + lane] = state * bc0.w;
                dtv = __shfl_sync(0xffffffffu, dtv4[g], hbase + ((l0+2) & 15), 32);
                state = fmaf(__expf(dtv*Ad), state, dtv*uq.z*bc1.x);
                psw[(q*4+2)*PSTR + lane] = state * bc1.y;
                dtv = __shfl_sync(0xffffffffu, dtv4[g], hbase + ((l0+3) & 15), 32);
                state = fmaf(__expf(dtv*Ad), state, dtv*uq.w*bc1.z);
                psw[(q*4+3)*PSTR + lane] = state * bc1.w;
            }
            __syncwarp();
            {
                int lo = g*16;
                const float4* row = (const float4*)&psw[n*PSTR + hbase];
                float4 v0 = row[0], v1 = row[1], v2 = row[2], v3 = row[3];
                float s = (((v0.x+v0.y)+(v0.z+v0.w)) + ((v1.x+v1.y)+(v1.z+v1.w)))
                        + (((v2.x+v2.y)+(v2.z+v2.w)) + ((v3.x+v3.y)+(v3.z+v3.w)));
                float2 gg = *(const float2*)&sgg[(lo + n)*32 + hw*2];
                sy[(lo + n)*16 + hw] = fmaf(s, gg.x, gg.y);
            }
            __syncwarp();
        }
        __syncthreads();

        // coalesced writeback
        {
            float4 v = *(const float4*)&sy[rl*16 + rq*4];
            *(float4*)(g_ymod + (size_t)(blbase + cc*SCH + rl)*DI + d0 + rq*4) = v;
        }
    }
}

// ---------------- LayerNorm (input already has residual added) ----------------
__global__ void __launch_bounds__(512)
ln_kernel(const float* __restrict__ gamma,
          const float* __restrict__ beta) {
    int wid  = threadIdx.x >> 5;
    int lane = threadIdx.x & 31;
    int bl   = blockIdx.x * 16 + wid;
    int col  = lane * 8;

    const float4* o4 = (const float4*)(g_out2 + (size_t)bl*DM + col);
    float t[8];
    float4 a = o4[0];
    t[0]=a.x; t[1]=a.y; t[2]=a.z; t[3]=a.w;
    a = o4[1];
    t[4]=a.x; t[5]=a.y; t[6]=a.z; t[7]=a.w;

    float v1 = 0.f, v2 = 0.f;
#pragma unroll
    for (int i = 0; i < 8; i++) { v1 += t[i]; v2 = fmaf(t[i], t[i], v2); }
#pragma unroll
    for (int o = 16; o > 0; o >>= 1) {
        v1 += __shfl_xor_sync(0xffffffffu, v1, o);
        v2 += __shfl_xor_sync(0xffffffffu, v2, o);
    }
    float mean = v1 * (1.f/DM);
    float var  = v2 * (1.f/DM) - mean*mean;
    float rs = rsqrtf(var + 1e-5f);

    float4 g0 = *(const float4*)(gamma + col);
    float4 g1 = *(const float4*)(gamma + col + 4);
    float4 b0 = *(const float4*)(beta  + col);
    float4 b1 = *(const float4*)(beta  + col + 4);

    float4 r0, r1;
    r0.x = (t[0]-mean)*rs*g0.x + b0.x;
    r0.y = (t[1]-mean)*rs*g0.y + b0.y;
    r0.z = (t[2]-mean)*rs*g0.z + b0.z;
    r0.w = (t[3]-mean)*rs*g0.w + b0.w;
    r1.x = (t[4]-mean)*rs*g1.x + b1.x;
    r1.y = (t[5]-mean)*rs*g1.y + b1.y;
    r1.z = (t[6]-mean)*rs*g1.z + b1.z;
    r1.w = (t[7]-mean)*rs*g1.w + b1.w;

    float4* out4 = (float4*)(g_h + (size_t)bl*DM + col);
    out4[0] = r0;
    out4[1] = r1;
}

// ---------------- Mean pool ----------------
__global__ void pool_kernel() {
    int b = blockIdx.x;
    int m = threadIdx.x;
    float s = 0.f;
    for (int l = 0; l < LSEQ; l++)
        s += g_h[(size_t)((b << 10) + l)*DM + m];
    g_pooled[b*DM + m] = s * (1.f/LSEQ);
}

// ---------------- Decoder ----------------
__global__ void dec_kernel(const float* __restrict__ w,
                           const float* __restrict__ bb,
                           float* __restrict__ out) {
    int i = threadIdx.x;
    if (i < BSZ*10) {
        int b = i / 10, o = i % 10;
        float acc = bb[o];
#pragma unroll 8
        for (int m = 0; m < DM; m++)
            acc = fmaf(g_pooled[b*DM + m], w[m*10 + o], acc);
        out[i] = acc;
    }
}

// ---------------- Launch ----------------
extern "C" void kernel_launch(void* const* d_in, const int* in_sizes, int n_in,
                              void* d_out, int out_size) {
    const float* x         = (const float*)d_in[0];
    const float* enc_w     = (const float*)d_in[1];
    const float* enc_b     = (const float*)d_in[2];
    const float* in_proj_w = (const float*)d_in[3];
    const float* conv_w    = (const float*)d_in[4];
    const float* conv_b    = (const float*)d_in[5];
    const float* x_proj_w  = (const float*)d_in[6];
    const float* dt_w      = (const float*)d_in[7];
    const float* dt_b      = (const float*)d_in[8];
    const float* A_log     = (const float*)d_in[9];
    const float* Dv        = (const float*)d_in[10];
    const float* out_proj_w= (const float*)d_in[11];
    const float* ln_g      = (const float*)d_in[12];
    const float* ln_b      = (const float*)d_in[13];
    const float* dec_w     = (const float*)d_in[14];
    const float* dec_b     = (const float*)d_in[15];

    float *p_h, *p_xz, *p_proj, *p_ymod, *p_out2;
    cudaGetSymbolAddress((void**)&p_h,    g_h);
    cudaGetSymbolAddress((void**)&p_xz,   g_xz);
    cudaGetSymbolAddress((void**)&p_proj, g_proj);
    cudaGetSymbolAddress((void**)&p_ymod, g_ymod);
    cudaGetSymbolAddress((void**)&p_out2, g_out2);

    enc_kernel<<<MROWS, DM>>>(x, enc_w, enc_b);

    for (int i = 0; i < NL; i++) {
        gemm_tf32_n128<<<dim3((2*DI)/128, MROWS/128), 256>>>(
            p_h, in_proj_w + (size_t)i*DM*2*DI, p_xz, MROWS, 2*DI, DM);

        xproj_conv_gemm<<<dim3(1, MROWS/64), 256>>>(
            p_xz, x_proj_w + (size_t)i*DI*PROJC, p_proj,
            conv_w + (size_t)i*DI*4, conv_b + (size_t)i*DI);

        scan_kernel<<<BSZ*32, 256>>>(A_log + (size_t)i*DI*NST, Dv + (size_t)i*DI,
                                     dt_w + (size_t)i*DTR*DI, dt_b + (size_t)i*DI,
                                     conv_w + (size_t)i*DI*4, conv_b + (size_t)i*DI);

        gemm_tf32_cp<128,1><<<dim3(DM/64, MROWS/128), 256>>>(
            p_ymod, out_proj_w + (size_t)i*DI*DM, p_out2, p_h, MROWS, DM, DI);

        ln_kernel<<<MROWS/16, 512>>>(ln_g + (size_t)i*DM, ln_b + (size_t)i*DM);
    }

    pool_kernel<<<BSZ, DM>>>();
    dec_kernel<<<1, 128>>>(dec_w, dec_b, (float*)d_out);
}